// round 1
// baseline (speedup 1.0000x reference)
#include <cuda_runtime.h>
#include <math.h>
#include <stdint.h>

#define NB   8
#define CIN  64
#define CO   128
#define HH0  256
#define WW0  256
#define HWSZ 65536
#define HD   128   // H/2
#define WD   128   // W/2

// ---------------- scratch (static device globals; no runtime alloc) ----------------
__device__ float g_wsn[CO*CIN*9];
__device__ float g_ratio[NB*HWSZ];
__device__ float g_mvalid[NB*HWSZ];
__device__ float g_y[(size_t)NB*CO*HWSZ];           // conv out, then GDN in-place
__device__ float g_lor[(size_t)NB*CO*HD*WW0];
__device__ float g_hir[(size_t)NB*CO*HD*WW0];
__device__ float g_mlo[NB*HD*WW0];
__device__ float g_mhi[NB*HD*WW0];

__constant__ float c_H0[9] = {
    0.026748757410810f, -0.016864118442875f, -0.078223266528990f,
    0.266864118442875f,  0.602949018236360f,  0.266864118442875f,
   -0.078223266528990f, -0.016864118442875f,  0.026748757410810f};
__constant__ float c_H1[7] = {
    0.091271763114250f, -0.057543526228500f, -0.591271763114250f,
    1.115087052457000f, -0.591271763114250f, -0.057543526228500f,
    0.091271763114250f};

// output offsets: (ll, m_ll, lh, hl, hh, m_lh, m_hl, m_hh)
#define SZ_BAND ((size_t)NB*CO*HD*WD)   // 16777216
#define SZ_MASK ((size_t)NB*HD*WD)      // 131072
#define OFS_LL   ((size_t)0)
#define OFS_MLL  (OFS_LL  + SZ_BAND)
#define OFS_LH   (OFS_MLL + SZ_MASK)
#define OFS_HL   (OFS_LH  + SZ_BAND)
#define OFS_HH   (OFS_HL  + SZ_BAND)
#define OFS_MLH  (OFS_HH  + SZ_BAND)
#define OFS_MHL  (OFS_MLH + SZ_MASK)
#define OFS_MHH  (OFS_MHL + SZ_MASK)

__device__ __forceinline__ int refl(int j, int n) {
    if (j < 0) j = -j;
    if (j >= n) j = 2*n - 2 - j;
    return j;
}

// ---------------- K0: spectral norm -> g_wsn ----------------
__global__ void k_sigma(const float* __restrict__ w, const float* __restrict__ u) {
    __shared__ float sv[576];
    __shared__ float red[576];
    __shared__ float s_bcast;
    int t = threadIdx.x;           // 576 threads

    // v = W^T u   (column t)
    float vj = 0.f;
    for (int o = 0; o < CO; ++o) vj += w[o*576 + t] * u[o];
    red[t] = vj*vj;
    sv[t] = vj;
    __syncthreads();
    if (t == 0) {
        float s = 0.f;
        for (int i = 0; i < 576; ++i) s += red[i];
        s_bcast = 1.f / (sqrtf(s) + 1e-12f);
    }
    __syncthreads();
    float vn = sv[t] * s_bcast;
    __syncthreads();
    sv[t] = vn;
    __syncthreads();

    // sigma = || W v ||
    if (t < CO) {
        float s = 0.f;
        for (int j = 0; j < 576; ++j) s += w[t*576 + j] * sv[j];
        red[t] = s*s;
    }
    __syncthreads();
    if (t == 0) {
        float s = 0.f;
        for (int i = 0; i < CO; ++i) s += red[i];
        s_bcast = 1.f / sqrtf(s);   // 1/sigma
    }
    __syncthreads();
    float inv_sigma = s_bcast;
    for (int i = t; i < CO*CIN*9; i += 576) g_wsn[i] = w[i] * inv_sigma;
}

// ---------------- K1: mask 3x3 box -> ratio + valid ----------------
__global__ void k_ratio(const float* __restrict__ mask) {
    int idx = blockIdx.x*256 + threadIdx.x;            // over NB*HWSZ
    int b = idx >> 16;
    int hw = idx & 65535;
    int h = hw >> 8, wx = hw & 255;
    const float* mb = mask + (size_t)b*HWSZ;
    float s = 0.f;
    #pragma unroll
    for (int dh = -1; dh <= 1; ++dh) {
        int h2 = h + dh;
        if (h2 < 0 || h2 >= HH0) continue;
        #pragma unroll
        for (int dw = -1; dw <= 1; ++dw) {
            int w2 = wx + dw;
            if (w2 < 0 || w2 >= WW0) continue;
            s += mb[h2*WW0 + w2];
        }
    }
    bool valid = s > 0.f;
    g_mvalid[idx] = valid ? 1.f : 0.f;
    g_ratio[idx]  = valid ? 9.f / fmaxf(s, 1e-8f) : 0.f;
}

// ---------------- K2: 3x3 partial conv (x*mask) * w_sn ----------------
// block: 32 o-chan x 8 h x 64 w, 256 threads; thread: 8 o x 8 px
__global__ void __launch_bounds__(256) k_conv(const float* __restrict__ x,
                                              const float* __restrict__ mask,
                                              const float* __restrict__ bias) {
    __shared__ float xs[10][68];
    __shared__ float ws[32*9];

    int wt = blockIdx.x * 64;
    int ht = blockIdx.y * 8;
    int bo = blockIdx.z;
    int b  = bo >> 2;
    int ob = (bo & 3) * 32;

    int t  = threadIdx.x;
    int wg = t & 7, hg = (t >> 3) & 7, og = t >> 6;

    float acc[8][8];
    #pragma unroll
    for (int i = 0; i < 8; ++i)
        #pragma unroll
        for (int j = 0; j < 8; ++j) acc[i][j] = 0.f;

    const float* xb = x    + (size_t)b*CIN*HWSZ;
    const float* mb = mask + (size_t)b*HWSZ;

    for (int c = 0; c < CIN; ++c) {
        __syncthreads();
        const float* xc = xb + (size_t)c*HWSZ;
        for (int i = t; i < 10*66; i += 256) {
            int r = i / 66, cc = i % 66;
            int h = ht - 1 + r, wx = wt - 1 + cc;
            float v = 0.f;
            if (h >= 0 && h < HH0 && wx >= 0 && wx < WW0)
                v = xc[h*WW0 + wx] * mb[h*WW0 + wx];
            xs[r][cc] = v;
        }
        for (int i = t; i < 288; i += 256) {
            int o = i / 9, k = i % 9;
            ws[i] = g_wsn[((size_t)(ob + o)*CIN + c)*9 + k];
        }
        __syncthreads();

        float in0[10], in1[10], in2[10];
        #pragma unroll
        for (int j = 0; j < 10; ++j) {
            in0[j] = xs[hg + 0][wg*8 + j];
            in1[j] = xs[hg + 1][wg*8 + j];
            in2[j] = xs[hg + 2][wg*8 + j];
        }
        #pragma unroll
        for (int oo = 0; oo < 8; ++oo) {
            const float* wp = &ws[(og*8 + oo)*9];
            float w0 = wp[0], w1 = wp[1], w2 = wp[2];
            float w3 = wp[3], w4 = wp[4], w5 = wp[5];
            float w6 = wp[6], w7 = wp[7], w8 = wp[8];
            #pragma unroll
            for (int p = 0; p < 8; ++p) {
                float s = acc[oo][p];
                s += w0*in0[p];  s += w1*in0[p+1]; s += w2*in0[p+2];
                s += w3*in1[p];  s += w4*in1[p+1]; s += w5*in1[p+2];
                s += w6*in2[p];  s += w7*in2[p+1]; s += w8*in2[p+2];
                acc[oo][p] = s;
            }
        }
    }

    // epilogue: renormalize + bias + mask
    int h = ht + hg;
    float rt[8];
    #pragma unroll
    for (int p = 0; p < 8; ++p) {
        int wx = wt + wg*8 + p;
        rt[p] = g_ratio[((size_t)b*HH0 + h)*WW0 + wx];
    }
    #pragma unroll
    for (int oo = 0; oo < 8; ++oo) {
        int o = ob + og*8 + oo;
        float bv = bias[o];
        float* yp = g_y + (((size_t)b*CO + o)*HH0 + h)*WW0 + wt + wg*8;
        #pragma unroll
        for (int p = 0; p < 8; ++p) {
            float r = rt[p];
            yp[p] = (r > 0.f) ? acc[oo][p]*r + bv : 0.f;
        }
    }
}

// ---------------- K3: GDN (in-place on g_y), tiled 128x128 GEMM per 128-pixel tile ----------
__global__ void __launch_bounds__(256) k_gdn(const float* __restrict__ gamma,
                                             const float* __restrict__ beta) {
    __shared__ float zs[16][128];
    __shared__ float gs[128][17];

    size_t p0 = (size_t)blockIdx.x * 128;     // global pixel tile (b*HWSZ + hw)
    int b   = (int)(p0 >> 16);
    int hw0 = (int)(p0 & 65535);
    int t = threadIdx.x;
    int px = t & 15, oy = t >> 4;

    float acc[8][8];
    #pragma unroll
    for (int i = 0; i < 8; ++i)
        #pragma unroll
        for (int j = 0; j < 8; ++j) acc[i][j] = 0.f;

    float* yb = g_y + (size_t)b*CO*HWSZ + hw0;

    for (int c0 = 0; c0 < CO; c0 += 16) {
        __syncthreads();
        for (int i = t; i < 2048; i += 256) {        // z = x^2 chunk [16][128]
            int k = i >> 7, p = i & 127;
            float v = yb[(size_t)(c0 + k)*HWSZ + p];
            zs[k][p] = v*v;
        }
        for (int i = t; i < 2048; i += 256) {        // gamma chunk [128][16]
            int o = i >> 4, k = i & 15;
            gs[o][k] = gamma[o*CO + c0 + k];
        }
        __syncthreads();
        #pragma unroll
        for (int k = 0; k < 16; ++k) {
            float a[8], bb[8];
            #pragma unroll
            for (int i = 0; i < 8; ++i) a[i] = gs[oy*8 + i][k];
            #pragma unroll
            for (int j = 0; j < 8; ++j) bb[j] = zs[k][px + 16*j];
            #pragma unroll
            for (int i = 0; i < 8; ++i)
                #pragma unroll
                for (int j = 0; j < 8; ++j) acc[i][j] += a[i]*bb[j];
        }
    }

    #pragma unroll
    for (int i = 0; i < 8; ++i) {
        int o = oy*8 + i;
        float bo = beta[o];
        #pragma unroll
        for (int j = 0; j < 8; ++j) {
            int p = px + 16*j;
            size_t ad = (size_t)o*HWSZ + p;
            float xv = yb[ad];
            float mv = g_mvalid[p0 + p];
            yb[ad] = xv * rsqrtf(bo + acc[i][j]) * mv;
        }
    }
}

// ---------------- K4: DWT row filters (H axis, stride 2, reflect) ----------------
__global__ void k_dwt_rows() {
    size_t idx = (size_t)blockIdx.x*256 + threadIdx.x;  // [B*C][HD][W]
    int wx = (int)(idx & 255);
    int hr = (int)((idx >> 8) & 127);
    int bc = (int)(idx >> 15);
    const float* col = g_y + (size_t)bc*HWSZ + wx;
    float r[9];
    #pragma unroll
    for (int k = 0; k < 9; ++k)
        r[k] = col[refl(2*hr + k - 4, HH0) * WW0];
    float lo = 0.f, hi = 0.f;
    #pragma unroll
    for (int k = 0; k < 9; ++k) lo += c_H0[k]*r[k];
    #pragma unroll
    for (int k = 0; k < 7; ++k) hi += c_H1[k]*r[k+1];
    g_lor[idx] = lo;
    g_hir[idx] = hi;
}

// ---------------- K5: DWT col filters -> 4 bands straight to d_out ----------------
__global__ void k_dwt_cols(float* __restrict__ out) {
    size_t idx = (size_t)blockIdx.x*256 + threadIdx.x;  // [B*C][HD][WD]
    int wr = (int)(idx & 127);
    int hr = (int)((idx >> 7) & 127);
    int bc = (int)(idx >> 14);
    const float* lrow = g_lor + ((size_t)bc*HD + hr)*WW0;
    const float* hrow = g_hir + ((size_t)bc*HD + hr)*WW0;
    float rl[9], rh[9];
    #pragma unroll
    for (int k = 0; k < 9; ++k) {
        int j = refl(2*wr + k - 4, WW0);
        rl[k] = lrow[j];
        rh[k] = hrow[j];
    }
    float ll = 0.f, lh = 0.f, hl = 0.f, hh = 0.f;
    #pragma unroll
    for (int k = 0; k < 9; ++k) { ll += c_H0[k]*rl[k]; hl += c_H0[k]*rh[k]; }
    #pragma unroll
    for (int k = 0; k < 7; ++k) { lh += c_H1[k]*rl[k+1]; hh += c_H1[k]*rh[k+1]; }
    out[OFS_LL + idx] = ll;
    out[OFS_LH + idx] = lh;
    out[OFS_HL + idx] = hl;
    out[OFS_HH + idx] = hh;
}

// ---------------- K6: mask downsample along H ----------------
__global__ void k_mask_rows() {
    int idx = blockIdx.x*256 + threadIdx.x;   // [B][HD][W]
    int wx = idx & 255;
    int hr = (idx >> 8) & 127;
    int b  = idx >> 15;
    const float* mb = g_mvalid + (size_t)b*HWSZ + wx;
    float s9 = 0.f, s7 = 0.f;
    #pragma unroll
    for (int k = 0; k < 9; ++k) {
        float v = mb[refl(2*hr + k - 4, HH0) * WW0];
        s9 += v;
        if (k >= 1 && k <= 7) s7 += v;
    }
    g_mlo[idx] = (s9 > 0.f) ? 1.f : 0.f;
    g_mhi[idx] = (s7 > 0.f) ? 1.f : 0.f;
}

// ---------------- K7: mask downsample along W -> d_out ----------------
__global__ void k_mask_cols(float* __restrict__ out) {
    int idx = blockIdx.x*256 + threadIdx.x;   // [B][HD][WD]
    int wr = idx & 127;
    int hr = (idx >> 7) & 127;
    int b  = idx >> 14;
    const float* lrow = g_mlo + ((size_t)b*HD + hr)*WW0;
    const float* hrow = g_mhi + ((size_t)b*HD + hr)*WW0;
    float s9l = 0.f, s7l = 0.f, s9h = 0.f, s7h = 0.f;
    #pragma unroll
    for (int k = 0; k < 9; ++k) {
        int j = refl(2*wr + k - 4, WW0);
        float vl = lrow[j], vh = hrow[j];
        s9l += vl; s9h += vh;
        if (k >= 1 && k <= 7) { s7l += vl; s7h += vh; }
    }
    out[OFS_MLL + idx] = (s9l > 0.f) ? 1.f : 0.f;
    out[OFS_MLH + idx] = (s7l > 0.f) ? 1.f : 0.f;
    out[OFS_MHL + idx] = (s9h > 0.f) ? 1.f : 0.f;
    out[OFS_MHH + idx] = (s7h > 0.f) ? 1.f : 0.f;
}

// ---------------- launch ----------------
extern "C" void kernel_launch(void* const* d_in, const int* in_sizes, int n_in,
                              void* d_out, int out_size) {
    const float* tensor = (const float*)d_in[0];
    const float* mask   = (const float*)d_in[1];
    const float* weight = (const float*)d_in[2];
    const float* bias   = (const float*)d_in[3];
    const float* u      = (const float*)d_in[4];
    const float* beta   = (const float*)d_in[5];
    const float* gamma  = (const float*)d_in[6];
    float* out = (float*)d_out;

    k_sigma<<<1, 576>>>(weight, u);
    k_ratio<<<(NB*HWSZ)/256, 256>>>(mask);
    k_conv<<<dim3(4, 32, NB*4), 256>>>(tensor, mask, bias);
    k_gdn<<<(NB*HWSZ)/128, 256>>>(gamma, beta);
    k_dwt_rows<<<(int)(((size_t)NB*CO*HD*WW0)/256), 256>>>();
    k_dwt_cols<<<(int)(((size_t)NB*CO*HD*WD)/256), 256>>>(out);
    k_mask_rows<<<(NB*HD*WW0)/256, 256>>>();
    k_mask_cols<<<(NB*HD*WD)/256, 256>>>(out);
}